// round 15
// baseline (speedup 1.0000x reference)
#include <cuda_runtime.h>
#include <cuda_fp16.h>
#include <cstdint>
#include <math.h>

typedef uint32_t u32;

#define BB 8
#define NN 4096
#define CC 128
#define QT 128              // query rows per CTA (8 warp-pairs x 16 rows)
#define KTT 128             // keys per tile (split 64/64 across a warp pair)
#define NTILE (NN / KTT)    // 32
// (1/sqrt(128)) * log2(e): S computed directly in log2 domain
#define QSCALE 0.12751743082f

__device__ __half g_q[BB * NN * CC];
__device__ __half g_k[BB * NN * CC];
__device__ __half g_v[BB * NN * CC];

// ---- attn smem: Q 32KB | K 3x32KB | V 3x32KB | BN 1KB = 225KB ----
#define QS_OFF  0u
#define KS_OFF  32768u
#define VS_OFF  131072u
#define BN_OFF  229376u
#define SMEM_ATTN 230400
// O-exchange overlays Q+K region after the final barrier (stride 528 = pad 16B)
#define OX_OFF  0u
#define LR_OFF  69632u
// ---- qkv smem ----
#define XS_OFF  0u
#define WS_OFF  32768u
#define SMEM_QKV 131072

// ---------------- helpers ----------------
__device__ __forceinline__ u32 s2u(const void* p) {
    u32 a; asm("{ .reg .u64 t; cvta.to.shared.u64 t, %1; cvt.u32.u64 %0, t; }" : "=r"(a) : "l"(p));
    return a;
}
__device__ __forceinline__ u32 so(u32 row, u32 c8) {      // 256B rows, XOR swizzle
    return row * 256u + ((c8 ^ (row & 7u)) * 16u);
}
__device__ __forceinline__ void cpa16(u32 dst, const void* src) {
    asm volatile("cp.async.cg.shared.global [%0], [%1], 16;" :: "r"(dst), "l"(src));
}
__device__ __forceinline__ void cp_commit() { asm volatile("cp.async.commit_group;" ::: "memory"); }
template <int N> __device__ __forceinline__ void cp_wait() {
    asm volatile("cp.async.wait_group %0;" :: "n"(N) : "memory");
}
__device__ __forceinline__ void ldsm4(u32 addr, u32* r) {
    asm volatile("ldmatrix.sync.aligned.m8n8.x4.shared.b16 {%0,%1,%2,%3}, [%4];"
                 : "=r"(r[0]), "=r"(r[1]), "=r"(r[2]), "=r"(r[3]) : "r"(addr));
}
__device__ __forceinline__ void ldsm4t(u32 addr, u32* r) {
    asm volatile("ldmatrix.sync.aligned.m8n8.x4.trans.shared.b16 {%0,%1,%2,%3}, [%4];"
                 : "=r"(r[0]), "=r"(r[1]), "=r"(r[2]), "=r"(r[3]) : "r"(addr));
}
// f32-accumulating f16 mma (PV, QKV)
__device__ __forceinline__ void mmaf(float* c, const u32* a, u32 b0, u32 b1) {
    asm volatile("mma.sync.aligned.m16n8k16.row.col.f32.f16.f16.f32 "
                 "{%0,%1,%2,%3}, {%4,%5,%6,%7}, {%8,%9}, {%0,%1,%2,%3};"
                 : "+f"(c[0]), "+f"(c[1]), "+f"(c[2]), "+f"(c[3])
                 : "r"(a[0]), "r"(a[1]), "r"(a[2]), "r"(a[3]), "r"(b0), "r"(b1));
}
// f16-accumulating f16 mma (S)
__device__ __forceinline__ void mmah(u32* c, const u32* a, u32 b0, u32 b1) {
    asm volatile("mma.sync.aligned.m16n8k16.row.col.f16.f16.f16.f16 "
                 "{%0,%1}, {%2,%3,%4,%5}, {%6,%7}, {%0,%1};"
                 : "+r"(c[0]), "+r"(c[1])
                 : "r"(a[0]), "r"(a[1]), "r"(a[2]), "r"(a[3]), "r"(b0), "r"(b1));
}
__device__ __forceinline__ u32 cvtf16(float hi, float lo) {   // d = {hi, lo}
    u32 d; asm("cvt.rn.f16x2.f32 %0, %1, %2;" : "=r"(d) : "f"(hi), "f"(lo)); return d;
}
__device__ __forceinline__ u32 ex2h2(u32 a) {
    u32 d; asm("ex2.approx.f16x2 %0, %1;" : "=r"(d) : "r"(a)); return d;
}
__device__ __forceinline__ u32 hadd2(u32 a, u32 b) {
    u32 d; asm("add.f16x2 %0, %1, %2;" : "=r"(d) : "r"(a), "r"(b)); return d;
}
__device__ __forceinline__ float2 h2f2(u32 a) {
    __half2 h; *reinterpret_cast<u32*>(&h) = a;
    return __half22float2(h);
}

// =====================================================================
// Kernel 1: QKV projection via f16 mma.sync (~22us, proven R12/R14).
// Q pre-scaled by (1/sqrt(C))*log2(e).
// =====================================================================
__global__ void __launch_bounds__(256, 1) qkv_mma(
    const float* __restrict__ x,
    const float* __restrict__ wq, const float* __restrict__ bq,
    const float* __restrict__ wk, const float* __restrict__ bk,
    const float* __restrict__ wv, const float* __restrict__ bv)
{
    extern __shared__ char smc[];
    const u32 sb = s2u(smc);
    const int tid = threadIdx.x, w = tid >> 5, lane = tid & 31;
    const int r8 = lane & 7, sel = lane >> 3;
    const int row0 = blockIdx.x * 128;

    #pragma unroll
    for (int i = 0; i < 8; i++) {
        int idx = tid + 256 * i; u32 r = (u32)(idx >> 4), c8 = (u32)(idx & 15);
        const float* p = x + (size_t)(row0 + r) * CC + 8 * c8;
        float4 a = *(const float4*)p;
        float4 b4 = *(const float4*)(p + 4);
        uint4 o;
        o.x = cvtf16(a.y, a.x);   o.y = cvtf16(a.w, a.z);
        o.z = cvtf16(b4.y, b4.x); o.w = cvtf16(b4.w, b4.z);
        *(uint4*)(smc + XS_OFF + so(r, c8)) = o;
    }
    const float* ws[3] = { wq, wk, wv };
    #pragma unroll
    for (int m = 0; m < 3; m++) {
        const float* wp = ws[m];
        #pragma unroll
        for (int i = 0; i < 8; i++) {
            int idx = tid + 256 * i; u32 r = (u32)(idx >> 4), c8 = (u32)(idx & 15);
            const float* p = wp + (size_t)r * CC + 8 * c8;
            float4 a = *(const float4*)p;
            float4 b4 = *(const float4*)(p + 4);
            uint4 o;
            o.x = cvtf16(a.y, a.x);   o.y = cvtf16(a.w, a.z);
            o.z = cvtf16(b4.y, b4.x); o.w = cvtf16(b4.w, b4.z);
            *(uint4*)(smc + WS_OFF + (u32)m * 32768u + so(r, c8)) = o;
        }
    }
    __syncthreads();

    u32 qa[8][4];
    #pragma unroll
    for (int s = 0; s < 8; s++) {
        u32 r = (u32)(w * 16 + r8 + (sel & 1) * 8);
        u32 ch = (u32)(2 * s + (sel >> 1));
        ldsm4(sb + XS_OFF + so(r, ch), qa[s]);
    }

    __half* outs[3] = { g_q, g_k, g_v };
    const float* biases[3] = { bq, bk, bv };
    const int rr = lane >> 2, cq = (lane & 3) * 2;
    const int ra = row0 + w * 16 + rr;

    #pragma unroll
    for (int m = 0; m < 3; m++) {
        const u32 wb = sb + WS_OFF + (u32)m * 32768u;
        const float qs = (m == 0) ? QSCALE : 1.0f;
        float acc[16][4];
        #pragma unroll
        for (int g = 0; g < 16; g++)
            { acc[g][0] = 0.f; acc[g][1] = 0.f; acc[g][2] = 0.f; acc[g][3] = 0.f; }

        #pragma unroll
        for (int s = 0; s < 8; s++) {
            u32 kr = (u32)(s * 16 + r8 + (sel & 1) * 8);
            #pragma unroll
            for (int gp = 0; gp < 8; gp++) {
                u32 ch = (u32)(2 * gp + (sel >> 1));
                u32 bf[4];
                ldsm4t(wb + so(kr, ch), bf);
                mmaf(acc[2 * gp],     qa[s], bf[0], bf[1]);
                mmaf(acc[2 * gp + 1], qa[s], bf[2], bf[3]);
            }
        }

        const float* bias = biases[m];
        __half* og = outs[m];
        #pragma unroll
        for (int g = 0; g < 16; g++) {
            int c = g * 8 + cq;
            float b0 = __ldg(bias + c), b1 = __ldg(bias + c + 1);
            u32 v0 = cvtf16((acc[g][1] + b1) * qs, (acc[g][0] + b0) * qs);
            u32 v1 = cvtf16((acc[g][3] + b1) * qs, (acc[g][2] + b0) * qs);
            *(u32*)&og[(size_t)ra * CC + c] = v0;
            *(u32*)&og[(size_t)(ra + 8) * CC + c] = v1;
        }
    }
}

// =====================================================================
// K+V 128-row tile loader (512 threads), buf in {0,1,2}
// =====================================================================
__device__ __forceinline__ void ldKV(u32 sb, const __half* kg, const __half* vg,
                                     int tid, int buf)
{
    u32 kb = sb + KS_OFF + (u32)buf * 32768u;
    u32 vb = sb + VS_OFF + (u32)buf * 32768u;
    #pragma unroll
    for (int i = 0; i < 4; i++) {
        int idx = tid + 512 * i; u32 row = (u32)(idx >> 4), c8 = (u32)(idx & 15);
        cpa16(kb + so(row, c8), kg + (size_t)row * CC + 8 * c8);
    }
    #pragma unroll
    for (int i = 0; i < 4; i++) {
        int idx = tid + 512 * i; u32 row = (u32)(idx >> 4), c8 = (u32)(idx & 15);
        cpa16(vb + so(row, c8), vg + (size_t)row * CC + 8 * c8);
    }
    cp_commit();
}

// =====================================================================
// Kernel 2: f16 flash attention, key-split warp pairs.
// grid (32, 8), 512 threads = 16 warps = 8 pairs x 16 query rows.
// Warp (pair, half): rows [pair*16, pair*16+16), keys [half*64, half*64+64)
// of each 128-key tile. Halves combine O + lr through smem at the end.
// =====================================================================
__global__ void __launch_bounds__(512, 1) attn_mma(
    const float* __restrict__ x,
    const float* __restrict__ gamma, const float* __restrict__ beta,
    const float* __restrict__ mmean, const float* __restrict__ mvar,
    float* __restrict__ out)
{
    extern __shared__ char smc[];
    const u32 sb = s2u(smc);
    const int tid = threadIdx.x, w = tid >> 5, lane = tid & 31;
    const int r8 = lane & 7, sel = lane >> 3;
    const int pair = w >> 1, half = w & 1;
    const int b = blockIdx.y, q0 = blockIdx.x * QT;
    const size_t base = (size_t)b * NN * CC;

    if (tid < 128) {
        float iv = gamma[tid] * rsqrtf(mvar[tid] + 1e-3f);
        ((float*)(smc + BN_OFF))[tid] = iv;
        ((float*)(smc + BN_OFF + 512))[tid] = beta[tid] - mmean[tid] * iv;
    }

    // prologue: Q + KV0 (group 0), KV1 (group 1)
    {
        const __half* qg = g_q + base + (size_t)q0 * CC;
        #pragma unroll
        for (int i = 0; i < 4; i++) {
            int idx = tid + 512 * i; u32 row = (u32)(idx >> 4), c8 = (u32)(idx & 15);
            cpa16(sb + QS_OFF + so(row, c8), qg + (size_t)row * CC + 8 * c8);
        }
    }
    ldKV(sb, g_k + base, g_v + base, tid, 0);
    ldKV(sb, g_k + base + (size_t)KTT * CC, g_v + base + (size_t)KTT * CC, tid, 1);

    float o[16][4];
    #pragma unroll
    for (int g = 0; g < 16; g++)
        { o[g][0] = 0.f; o[g][1] = 0.f; o[g][2] = 0.f; o[g][3] = 0.f; }
    float lr0 = 0.f, lr1 = 0.f;

    const u32 qrow = (u32)(pair * 16 + r8 + (sel & 1) * 8);
    const u32 kq   = (u32)(half * 64 + r8 + (sel >> 1) * 8);  // S-phase K row base
    const u32 kv   = (u32)(half * 64 + r8 + (sel & 1) * 8);   // PV-phase V row base

    #pragma unroll 1
    for (int j = 0; j < NTILE; j++) {
        cp_wait<0>();
        __syncthreads();     // KV(j) ready AND all warps done with tile j-1
        if (j + 2 < NTILE) {
            int nb = j + 2; nb -= (nb >= 3) ? ((nb >= 6) ? ((nb >= 9) ? 9 : 6) : 3) : 0;
            ldKV(sb, g_k + base + (size_t)(j + 2) * KTT * CC,
                     g_v + base + (size_t)(j + 2) * KTT * CC, tid, (j + 2) % 3);
        }
        const u32 kb = sb + KS_OFF + (u32)(j % 3) * 32768u;
        const u32 vb = sb + VS_OFF + (u32)(j % 3) * 32768u;

        // ---- S = Q K^T over this warp's 64 keys (f16 accumulators) ----
        u32 cur[8][2];
        #pragma unroll
        for (int g = 0; g < 8; g++) { cur[g][0] = 0u; cur[g][1] = 0u; }
        #pragma unroll
        for (int s = 0; s < 8; s++) {
            u32 qa4[4];
            ldsm4(sb + QS_OFF + so(qrow, (u32)(2 * s + (sel >> 1))), qa4);
            u32 ch = (u32)(2 * s + (sel & 1));
            #pragma unroll
            for (int gp = 0; gp < 4; gp++) {
                u32 kf[4];
                ldsm4(kb + so(kq + (u32)(gp * 16), ch), kf);
                mmah(cur[2 * gp],     qa4, kf[0], kf[1]);
                mmah(cur[2 * gp + 1], qa4, kf[2], kf[3]);
            }
        }

        // ---- softmax in place + f16 row sums ----
        u32 hs0 = 0u, hs1 = 0u;
        #pragma unroll
        for (int g = 0; g < 8; g++) {
            cur[g][0] = ex2h2(cur[g][0]);
            cur[g][1] = ex2h2(cur[g][1]);
            hs0 = hadd2(hs0, cur[g][0]);
            hs1 = hadd2(hs1, cur[g][1]);
        }
        float2 f0 = h2f2(hs0), f1 = h2f2(hs1);
        lr0 += f0.x + f0.y;
        lr1 += f1.x + f1.y;

        // ---- O += P V over this warp's 64 keys ----
        #pragma unroll
        for (int s = 0; s < 4; s++) {
            u32 pa[4] = { cur[2 * s][0], cur[2 * s][1], cur[2 * s + 1][0], cur[2 * s + 1][1] };
            u32 key = kv + (u32)(s * 16);
            #pragma unroll
            for (int gp = 0; gp < 8; gp++) {
                u32 vf[4];
                ldsm4t(vb + so(key, (u32)(2 * gp + (sel >> 1))), vf);
                mmaf(o[2 * gp],     pa, vf[0], vf[1]);
                mmaf(o[2 * gp + 1], pa, vf[2], vf[3]);
            }
        }
    }

    // ---- lr in-warp reduce (over the 4 col-lanes) ----
    lr0 += __shfl_xor_sync(0xffffffffu, lr0, 1);
    lr0 += __shfl_xor_sync(0xffffffffu, lr0, 2);
    lr1 += __shfl_xor_sync(0xffffffffu, lr1, 1);
    lr1 += __shfl_xor_sync(0xffffffffu, lr1, 2);

    const int rr = lane >> 2, cq = (lane & 3) * 2;
    const int lrow0 = pair * 16 + rr, lrow1 = lrow0 + 8;

    // ---- combine halves: half 0 publishes O + lr, half 1 finishes ----
    __syncthreads();          // everyone done with K/V/Q smem
    if (half == 0) {
        #pragma unroll
        for (int g = 0; g < 16; g++) {
            int c = g * 8 + cq;
            *(float2*)(smc + OX_OFF + (u32)lrow0 * 528u + (u32)c * 4u) = make_float2(o[g][0], o[g][1]);
            *(float2*)(smc + OX_OFF + (u32)lrow1 * 528u + (u32)c * 4u) = make_float2(o[g][2], o[g][3]);
        }
        if ((lane & 3) == 0) {
            ((float*)(smc + LR_OFF))[lrow0] = lr0;
            ((float*)(smc + LR_OFF))[lrow1] = lr1;
        }
    }
    __syncthreads();
    if (half == 1) {
        const float il0 = 1.0f / (lr0 + ((const float*)(smc + LR_OFF))[lrow0]);
        const float il1 = 1.0f / (lr1 + ((const float*)(smc + LR_OFF))[lrow1]);
        const float* invc = (const float*)(smc + BN_OFF);
        const float* addc = (const float*)(smc + BN_OFF + 512);
        const int row0g = q0 + lrow0, row1g = q0 + lrow1;
        #pragma unroll
        for (int g = 0; g < 16; g++) {
            int c = g * 8 + cq;
            float2 p0 = *(const float2*)(smc + OX_OFF + (u32)lrow0 * 528u + (u32)c * 4u);
            float2 p1 = *(const float2*)(smc + OX_OFF + (u32)lrow1 * 528u + (u32)c * 4u);
            float2 x0 = *(const float2*)&x[base + (size_t)row0g * CC + c];
            float2 x1 = *(const float2*)&x[base + (size_t)row1g * CC + c];
            float2 v0, v1;
            v0.x = ((o[g][0] + p0.x) * il0 + x0.x) * invc[c]     + addc[c];
            v0.y = ((o[g][1] + p0.y) * il0 + x0.y) * invc[c + 1] + addc[c + 1];
            v1.x = ((o[g][2] + p1.x) * il1 + x1.x) * invc[c]     + addc[c];
            v1.y = ((o[g][3] + p1.y) * il1 + x1.y) * invc[c + 1] + addc[c + 1];
            *(float2*)&out[base + (size_t)row0g * CC + c] = v0;
            *(float2*)&out[base + (size_t)row1g * CC + c] = v1;
        }
    }
}

// =====================================================================
extern "C" void kernel_launch(void* const* d_in, const int* in_sizes, int n_in,
                              void* d_out, int out_size)
{
    const float* x     = (const float*)d_in[0];
    const float* wq    = (const float*)d_in[1];
    const float* bq    = (const float*)d_in[2];
    const float* wk    = (const float*)d_in[3];
    const float* bk    = (const float*)d_in[4];
    const float* wv    = (const float*)d_in[5];
    const float* bv    = (const float*)d_in[6];
    const float* gamma = (const float*)d_in[7];
    const float* beta  = (const float*)d_in[8];
    const float* mmean = (const float*)d_in[9];
    const float* mvar  = (const float*)d_in[10];
    float* out = (float*)d_out;

    cudaFuncSetAttribute(qkv_mma, cudaFuncAttributeMaxDynamicSharedMemorySize, SMEM_QKV);
    cudaFuncSetAttribute(attn_mma, cudaFuncAttributeMaxDynamicSharedMemorySize, SMEM_ATTN);

    qkv_mma<<<(BB * NN) / 128, 256, SMEM_QKV>>>(x, wq, bq, wk, bk, wv, bv);
    attn_mma<<<dim3(NN / QT, BB), 512, SMEM_ATTN>>>(x, gamma, beta, mmean, mvar, out);
}

// round 16
// speedup vs baseline: 1.0485x; 1.0485x over previous
#include <cuda_runtime.h>
#include <cuda_fp16.h>
#include <cstdint>
#include <math.h>

typedef uint32_t u32;

#define BB 8
#define NN 4096
#define CC 128
#define QT 128              // query rows per CTA (8 warps x 16 rows)
#define KTT 64              // keys per tile
#define NTILE (NN / KTT)    // 64
// (1/sqrt(128)) * log2(e): S computed directly in log2 domain
#define QSCALE 0.12751743082f

__device__ __half g_q[BB * NN * CC];
__device__ __half g_k[BB * NN * CC];
__device__ __half g_v[BB * NN * CC];

// ---- attn smem (per CTA): Q 32KB | K 2x16KB | V 2x16KB | BN 1KB = 97KB ----
#define QS_OFF  0u
#define KS_OFF  32768u
#define VS_OFF  65536u
#define BN_OFF  98304u
#define SMEM_ATTN 99328
// ---- qkv smem ----
#define XS_OFF  0u
#define WS_OFF  32768u
#define SMEM_QKV 131072

// ---------------- helpers ----------------
__device__ __forceinline__ u32 s2u(const void* p) {
    u32 a; asm("{ .reg .u64 t; cvta.to.shared.u64 t, %1; cvt.u32.u64 %0, t; }" : "=r"(a) : "l"(p));
    return a;
}
__device__ __forceinline__ u32 so(u32 row, u32 c8) {      // 256B rows, XOR swizzle
    return row * 256u + ((c8 ^ (row & 7u)) * 16u);
}
__device__ __forceinline__ void cpa16(u32 dst, const void* src) {
    asm volatile("cp.async.cg.shared.global [%0], [%1], 16;" :: "r"(dst), "l"(src));
}
__device__ __forceinline__ void cp_commit() { asm volatile("cp.async.commit_group;" ::: "memory"); }
template <int N> __device__ __forceinline__ void cp_wait() {
    asm volatile("cp.async.wait_group %0;" :: "n"(N) : "memory");
}
__device__ __forceinline__ void ldsm4(u32 addr, u32* r) {
    asm volatile("ldmatrix.sync.aligned.m8n8.x4.shared.b16 {%0,%1,%2,%3}, [%4];"
                 : "=r"(r[0]), "=r"(r[1]), "=r"(r[2]), "=r"(r[3]) : "r"(addr));
}
__device__ __forceinline__ void ldsm4t(u32 addr, u32* r) {
    asm volatile("ldmatrix.sync.aligned.m8n8.x4.trans.shared.b16 {%0,%1,%2,%3}, [%4];"
                 : "=r"(r[0]), "=r"(r[1]), "=r"(r[2]), "=r"(r[3]) : "r"(addr));
}
// f32-accumulating f16 mma (PV, QKV)
__device__ __forceinline__ void mmaf(float* c, const u32* a, u32 b0, u32 b1) {
    asm volatile("mma.sync.aligned.m16n8k16.row.col.f32.f16.f16.f32 "
                 "{%0,%1,%2,%3}, {%4,%5,%6,%7}, {%8,%9}, {%0,%1,%2,%3};"
                 : "+f"(c[0]), "+f"(c[1]), "+f"(c[2]), "+f"(c[3])
                 : "r"(a[0]), "r"(a[1]), "r"(a[2]), "r"(a[3]), "r"(b0), "r"(b1));
}
// f16-accumulating f16 mma (S)
__device__ __forceinline__ void mmah(u32* c, const u32* a, u32 b0, u32 b1) {
    asm volatile("mma.sync.aligned.m16n8k16.row.col.f16.f16.f16.f16 "
                 "{%0,%1}, {%2,%3,%4,%5}, {%6,%7}, {%0,%1};"
                 : "+r"(c[0]), "+r"(c[1])
                 : "r"(a[0]), "r"(a[1]), "r"(a[2]), "r"(a[3]), "r"(b0), "r"(b1));
}
__device__ __forceinline__ u32 cvtf16(float hi, float lo) {   // d = {hi, lo}
    u32 d; asm("cvt.rn.f16x2.f32 %0, %1, %2;" : "=r"(d) : "f"(hi), "f"(lo)); return d;
}
__device__ __forceinline__ u32 ex2h2(u32 a) {
    u32 d; asm("ex2.approx.f16x2 %0, %1;" : "=r"(d) : "r"(a)); return d;
}
__device__ __forceinline__ u32 hadd2(u32 a, u32 b) {
    u32 d; asm("add.f16x2 %0, %1, %2;" : "=r"(d) : "r"(a), "r"(b)); return d;
}
__device__ __forceinline__ float2 h2f2(u32 a) {
    __half2 h; *reinterpret_cast<u32*>(&h) = a;
    return __half22float2(h);
}

// =====================================================================
// Kernel 1: QKV projection via f16 mma.sync (~22us, proven R12/R14).
// Q pre-scaled by (1/sqrt(C))*log2(e).
// =====================================================================
__global__ void __launch_bounds__(256, 1) qkv_mma(
    const float* __restrict__ x,
    const float* __restrict__ wq, const float* __restrict__ bq,
    const float* __restrict__ wk, const float* __restrict__ bk,
    const float* __restrict__ wv, const float* __restrict__ bv)
{
    extern __shared__ char smc[];
    const u32 sb = s2u(smc);
    const int tid = threadIdx.x, w = tid >> 5, lane = tid & 31;
    const int r8 = lane & 7, sel = lane >> 3;
    const int row0 = blockIdx.x * 128;

    #pragma unroll
    for (int i = 0; i < 8; i++) {
        int idx = tid + 256 * i; u32 r = (u32)(idx >> 4), c8 = (u32)(idx & 15);
        const float* p = x + (size_t)(row0 + r) * CC + 8 * c8;
        float4 a = *(const float4*)p;
        float4 b4 = *(const float4*)(p + 4);
        uint4 o;
        o.x = cvtf16(a.y, a.x);   o.y = cvtf16(a.w, a.z);
        o.z = cvtf16(b4.y, b4.x); o.w = cvtf16(b4.w, b4.z);
        *(uint4*)(smc + XS_OFF + so(r, c8)) = o;
    }
    const float* ws[3] = { wq, wk, wv };
    #pragma unroll
    for (int m = 0; m < 3; m++) {
        const float* wp = ws[m];
        #pragma unroll
        for (int i = 0; i < 8; i++) {
            int idx = tid + 256 * i; u32 r = (u32)(idx >> 4), c8 = (u32)(idx & 15);
            const float* p = wp + (size_t)r * CC + 8 * c8;
            float4 a = *(const float4*)p;
            float4 b4 = *(const float4*)(p + 4);
            uint4 o;
            o.x = cvtf16(a.y, a.x);   o.y = cvtf16(a.w, a.z);
            o.z = cvtf16(b4.y, b4.x); o.w = cvtf16(b4.w, b4.z);
            *(uint4*)(smc + WS_OFF + (u32)m * 32768u + so(r, c8)) = o;
        }
    }
    __syncthreads();

    u32 qa[8][4];
    #pragma unroll
    for (int s = 0; s < 8; s++) {
        u32 r = (u32)(w * 16 + r8 + (sel & 1) * 8);
        u32 ch = (u32)(2 * s + (sel >> 1));
        ldsm4(sb + XS_OFF + so(r, ch), qa[s]);
    }

    __half* outs[3] = { g_q, g_k, g_v };
    const float* biases[3] = { bq, bk, bv };
    const int rr = lane >> 2, cq = (lane & 3) * 2;
    const int ra = row0 + w * 16 + rr;

    #pragma unroll
    for (int m = 0; m < 3; m++) {
        const u32 wb = sb + WS_OFF + (u32)m * 32768u;
        const float qs = (m == 0) ? QSCALE : 1.0f;
        float acc[16][4];
        #pragma unroll
        for (int g = 0; g < 16; g++)
            { acc[g][0] = 0.f; acc[g][1] = 0.f; acc[g][2] = 0.f; acc[g][3] = 0.f; }

        #pragma unroll
        for (int s = 0; s < 8; s++) {
            u32 kr = (u32)(s * 16 + r8 + (sel & 1) * 8);
            #pragma unroll
            for (int gp = 0; gp < 8; gp++) {
                u32 ch = (u32)(2 * gp + (sel >> 1));
                u32 bf[4];
                ldsm4t(wb + so(kr, ch), bf);
                mmaf(acc[2 * gp],     qa[s], bf[0], bf[1]);
                mmaf(acc[2 * gp + 1], qa[s], bf[2], bf[3]);
            }
        }

        const float* bias = biases[m];
        __half* og = outs[m];
        #pragma unroll
        for (int g = 0; g < 16; g++) {
            int c = g * 8 + cq;
            float b0 = __ldg(bias + c), b1 = __ldg(bias + c + 1);
            u32 v0 = cvtf16((acc[g][1] + b1) * qs, (acc[g][0] + b0) * qs);
            u32 v1 = cvtf16((acc[g][3] + b1) * qs, (acc[g][2] + b0) * qs);
            *(u32*)&og[(size_t)ra * CC + c] = v0;
            *(u32*)&og[(size_t)(ra + 8) * CC + c] = v1;
        }
    }
}

// =====================================================================
// K+V 64-row tile loader (256 threads), buf in {0,1}
// =====================================================================
__device__ __forceinline__ void ldKV(u32 sb, const __half* kg, const __half* vg,
                                     int tid, int buf)
{
    u32 kb = sb + KS_OFF + (u32)buf * 16384u;
    u32 vb = sb + VS_OFF + (u32)buf * 16384u;
    #pragma unroll
    for (int i = 0; i < 4; i++) {
        int idx = tid + 256 * i; u32 row = (u32)(idx >> 4), c8 = (u32)(idx & 15);
        cpa16(kb + so(row, c8), kg + (size_t)row * CC + 8 * c8);
    }
    #pragma unroll
    for (int i = 0; i < 4; i++) {
        int idx = tid + 256 * i; u32 row = (u32)(idx >> 4), c8 = (u32)(idx & 15);
        cpa16(vb + so(row, c8), vg + (size_t)row * CC + 8 * c8);
    }
    cp_commit();
}

// =====================================================================
// Kernel 2: f16 flash attention, f16-acc S, 2 co-resident CTAs per SM.
// grid (32, 8), 256 threads (8 warps x 16 query rows), <=128 regs.
// Double-buffered KV with prefetch distance 1, one barrier per tile.
// The PEER CTA on the same SM fills softmax/barrier bubbles.
// =====================================================================
__global__ void __launch_bounds__(256, 2) attn_mma(
    const float* __restrict__ x,
    const float* __restrict__ gamma, const float* __restrict__ beta,
    const float* __restrict__ mmean, const float* __restrict__ mvar,
    float* __restrict__ out)
{
    extern __shared__ char smc[];
    const u32 sb = s2u(smc);
    const int tid = threadIdx.x, w = tid >> 5, lane = tid & 31;
    const int r8 = lane & 7, sel = lane >> 3;
    const int b = blockIdx.y, q0 = blockIdx.x * QT;
    const size_t base = (size_t)b * NN * CC;

    if (tid < 128) {
        float iv = gamma[tid] * rsqrtf(mvar[tid] + 1e-3f);
        ((float*)(smc + BN_OFF))[tid] = iv;
        ((float*)(smc + BN_OFF + 512))[tid] = beta[tid] - mmean[tid] * iv;
    }

    // prologue: Q + KV0 in group 0
    {
        const __half* qg = g_q + base + (size_t)q0 * CC;
        #pragma unroll
        for (int i = 0; i < 8; i++) {
            int idx = tid + 256 * i; u32 row = (u32)(idx >> 4), c8 = (u32)(idx & 15);
            cpa16(sb + QS_OFF + so(row, c8), qg + (size_t)row * CC + 8 * c8);
        }
    }
    ldKV(sb, g_k + base, g_v + base, tid, 0);

    float o[16][4];
    #pragma unroll
    for (int g = 0; g < 16; g++)
        { o[g][0] = 0.f; o[g][1] = 0.f; o[g][2] = 0.f; o[g][3] = 0.f; }
    float lr0 = 0.f, lr1 = 0.f;

    const u32 qrow = (u32)(w * 16 + r8 + (sel & 1) * 8);
    const u32 krow = (u32)(r8 + (sel >> 1) * 8);     // S-phase K row base
    const u32 vrow = (u32)(r8 + (sel & 1) * 8);      // PV-phase V row base

    #pragma unroll 1
    for (int j = 0; j < NTILE; j++) {
        cp_wait<0>();
        __syncthreads();     // KV(j) ready AND all warps done reading buf (j+1)&1
        if (j + 1 < NTILE)
            ldKV(sb, g_k + base + (size_t)(j + 1) * KTT * CC,
                     g_v + base + (size_t)(j + 1) * KTT * CC, tid, (j + 1) & 1);
        else
            cp_commit();
        const u32 kb = sb + KS_OFF + (u32)(j & 1) * 16384u;
        const u32 vb = sb + VS_OFF + (u32)(j & 1) * 16384u;

        // ---- S = Q K^T over 64 keys (f16 accumulators) ----
        u32 cur[8][2];
        #pragma unroll
        for (int g = 0; g < 8; g++) { cur[g][0] = 0u; cur[g][1] = 0u; }
        #pragma unroll
        for (int s = 0; s < 8; s++) {
            u32 qa4[4];
            ldsm4(sb + QS_OFF + so(qrow, (u32)(2 * s + (sel >> 1))), qa4);
            u32 ch = (u32)(2 * s + (sel & 1));
            #pragma unroll
            for (int gp = 0; gp < 4; gp++) {
                u32 kf[4];
                ldsm4(kb + so(krow + (u32)(gp * 16), ch), kf);
                mmah(cur[2 * gp],     qa4, kf[0], kf[1]);
                mmah(cur[2 * gp + 1], qa4, kf[2], kf[3]);
            }
        }

        // ---- softmax in place + f16 row sums ----
        u32 hs0 = 0u, hs1 = 0u;
        #pragma unroll
        for (int g = 0; g < 8; g++) {
            cur[g][0] = ex2h2(cur[g][0]);
            cur[g][1] = ex2h2(cur[g][1]);
            hs0 = hadd2(hs0, cur[g][0]);
            hs1 = hadd2(hs1, cur[g][1]);
        }
        float2 f0 = h2f2(hs0), f1 = h2f2(hs1);
        lr0 += f0.x + f0.y;
        lr1 += f1.x + f1.y;

        // ---- O += P V over 64 keys ----
        #pragma unroll
        for (int s = 0; s < 4; s++) {
            u32 pa[4] = { cur[2 * s][0], cur[2 * s][1], cur[2 * s + 1][0], cur[2 * s + 1][1] };
            u32 key = vrow + (u32)(s * 16);
            #pragma unroll
            for (int gp = 0; gp < 8; gp++) {
                u32 vf[4];
                ldsm4t(vb + so(key, (u32)(2 * gp + (sel >> 1))), vf);
                mmaf(o[2 * gp],     pa, vf[0], vf[1]);
                mmaf(o[2 * gp + 1], pa, vf[2], vf[3]);
            }
        }
    }

    // ---- epilogue ----
    lr0 += __shfl_xor_sync(0xffffffffu, lr0, 1);
    lr0 += __shfl_xor_sync(0xffffffffu, lr0, 2);
    lr1 += __shfl_xor_sync(0xffffffffu, lr1, 1);
    lr1 += __shfl_xor_sync(0xffffffffu, lr1, 2);
    const float il0 = 1.0f / lr0, il1 = 1.0f / lr1;

    const float* invc = (const float*)(smc + BN_OFF);
    const float* addc = (const float*)(smc + BN_OFF + 512);
    const int rr = lane >> 2, cq = (lane & 3) * 2;
    const int row0g = q0 + w * 16 + rr, row1g = row0g + 8;

    #pragma unroll
    for (int g = 0; g < 16; g++) {
        int c = g * 8 + cq;
        float2 x0 = *(const float2*)&x[base + (size_t)row0g * CC + c];
        float2 x1 = *(const float2*)&x[base + (size_t)row1g * CC + c];
        float2 v0, v1;
        v0.x = (o[g][0] * il0 + x0.x) * invc[c]     + addc[c];
        v0.y = (o[g][1] * il0 + x0.y) * invc[c + 1] + addc[c + 1];
        v1.x = (o[g][2] * il1 + x1.x) * invc[c]     + addc[c];
        v1.y = (o[g][3] * il1 + x1.y) * invc[c + 1] + addc[c + 1];
        *(float2*)&out[base + (size_t)row0g * CC + c] = v0;
        *(float2*)&out[base + (size_t)row1g * CC + c] = v1;
    }
}

// =====================================================================
extern "C" void kernel_launch(void* const* d_in, const int* in_sizes, int n_in,
                              void* d_out, int out_size)
{
    const float* x     = (const float*)d_in[0];
    const float* wq    = (const float*)d_in[1];
    const float* bq    = (const float*)d_in[2];
    const float* wk    = (const float*)d_in[3];
    const float* bk    = (const float*)d_in[4];
    const float* wv    = (const float*)d_in[5];
    const float* bv    = (const float*)d_in[6];
    const float* gamma = (const float*)d_in[7];
    const float* beta  = (const float*)d_in[8];
    const float* mmean = (const float*)d_in[9];
    const float* mvar  = (const float*)d_in[10];
    float* out = (float*)d_out;

    cudaFuncSetAttribute(qkv_mma, cudaFuncAttributeMaxDynamicSharedMemorySize, SMEM_QKV);
    cudaFuncSetAttribute(attn_mma, cudaFuncAttributeMaxDynamicSharedMemorySize, SMEM_ATTN);

    qkv_mma<<<(BB * NN) / 128, 256, SMEM_QKV>>>(x, wq, bq, wk, bk, wv, bv);
    attn_mma<<<dim3(NN / QT, BB), 256, SMEM_ATTN>>>(x, gamma, beta, mmean, mvar, out);
}